// round 2
// baseline (speedup 1.0000x reference)
#include <cuda_runtime.h>
#include <math.h>

#define NB 4096
#define ND 1024
#define NH 2048
#define NC 1000
#define NT 819200
#define NF 32

// ---------------- scratch (static device globals; no allocation) ----------------
__device__ float g_means[NB * NF];                 // [B, 32]
__device__ float g_combined[(size_t)NB * ND];      // [B, 1024]
__device__ float g_hidden[(size_t)NB * NH];        // [B, 2048]
__device__ float g_logits[(size_t)NB * NC];        // [B, 1000]
__device__ float g_scalar[NB];
__device__ float g_row_lv[NB];
__device__ float g_row_acc[NB];

// ---------------- segment mean: one block per segment, deterministic ----------------
__global__ void __launch_bounds__(256) seg_mean_kernel(const float* __restrict__ var_flat,
                                                       const int* __restrict__ seg) {
    __shared__ int s_bounds[2];
    __shared__ float red[8][32];
    const int b = blockIdx.x;
    const int tid = threadIdx.x;
    if (tid < 2) {
        const int v = b + tid;
        int lo = 0, hi = NT;
        while (lo < hi) {
            int mid = (lo + hi) >> 1;
            if (seg[mid] < v) lo = mid + 1; else hi = mid;
        }
        s_bounds[tid] = lo;
    }
    __syncthreads();
    const int start = s_bounds[0];
    const int end   = s_bounds[1];
    const int f = tid & 31;
    const int w = tid >> 5;
    float acc = 0.0f;
    for (int r = start + w; r < end; r += 8)
        acc += var_flat[(size_t)r * NF + f];
    red[w][f] = acc;
    __syncthreads();
    if (w == 0) {
        float s = 0.0f;
#pragma unroll
        for (int i = 0; i < 8; i++) s += red[i][f];
        const float cnt = fmaxf((float)(end - start), 1.0f);
        g_means[b * NF + f] = s / cnt;
    }
}

// ---------------- tiled fp32 NT SGEMM: C[M,N] = A[M,K] * W[N,K]^T + bias (+addend) ----------------
// BM=BN=128, BK=8, 256 threads, 8x8 per-thread microtile. M % 128 == 0, K % 8 == 0 required.
template <bool RELU, bool HAS_ADD>
__global__ void __launch_bounds__(256, 2) sgemm_nt(const float* __restrict__ A,
                                                   const float* __restrict__ W,
                                                   const float* __restrict__ bias,
                                                   const float* __restrict__ addend,
                                                   float* __restrict__ C,
                                                   int M, int N, int K) {
    __shared__ float As[8][128];
    __shared__ float Bs[8][128];

    const int bm  = blockIdx.y * 128;
    const int bn  = blockIdx.x * 128;
    const int tid = threadIdx.x;

    const int lrow = tid >> 1;          // 0..127
    const int lcol = (tid & 1) * 4;     // 0 or 4
    const int tx   = tid & 15;          // 0..15
    const int ty   = tid >> 4;          // 0..15

    float acc[8][8];
#pragma unroll
    for (int i = 0; i < 8; i++)
#pragma unroll
        for (int j = 0; j < 8; j++) acc[i][j] = 0.0f;

    const float* Ap = A + (size_t)(bm + lrow) * K + lcol;
    const int wrow = bn + lrow;
    const float* Wp = W + (size_t)wrow * K + lcol;
    const bool wvalid = (wrow < N);

    for (int k0 = 0; k0 < K; k0 += 8) {
        const float4 av = *(const float4*)(Ap + k0);
        float4 wv = make_float4(0.f, 0.f, 0.f, 0.f);
        if (wvalid) wv = *(const float4*)(Wp + k0);

        As[lcol + 0][lrow] = av.x; As[lcol + 1][lrow] = av.y;
        As[lcol + 2][lrow] = av.z; As[lcol + 3][lrow] = av.w;
        Bs[lcol + 0][lrow] = wv.x; Bs[lcol + 1][lrow] = wv.y;
        Bs[lcol + 2][lrow] = wv.z; Bs[lcol + 3][lrow] = wv.w;
        __syncthreads();

#pragma unroll
        for (int k = 0; k < 8; k++) {
            float a[8], bb[8];
#pragma unroll
            for (int i = 0; i < 8; i++) a[i] = As[k][ty * 8 + i];
#pragma unroll
            for (int j = 0; j < 8; j++) bb[j] = Bs[k][tx * 8 + j];
#pragma unroll
            for (int i = 0; i < 8; i++)
#pragma unroll
                for (int j = 0; j < 8; j++) acc[i][j] += a[i] * bb[j];
        }
        __syncthreads();
    }

#pragma unroll
    for (int i = 0; i < 8; i++) {
        const int m = bm + ty * 8 + i;
#pragma unroll
        for (int j = 0; j < 8; j++) {
            const int n = bn + tx * 8 + j;
            if (n < N) {
                float v = acc[i][j] + bias[n];
                if (HAS_ADD) v += addend[(size_t)m * N + n];
                if (RELU) v = fmaxf(v, 0.0f);
                C[(size_t)m * N + n] = v;
            }
        }
    }
}

// ---------------- scalar head: warp per row, dot(hidden_row, Ws) + bs ----------------
__global__ void __launch_bounds__(256) scalar_kernel(const float* __restrict__ Ws,
                                                     const float* __restrict__ bs) {
    const int warp = threadIdx.x >> 5;
    const int lane = threadIdx.x & 31;
    const int b = blockIdx.x * 8 + warp;
    const float* hrow = g_hidden + (size_t)b * NH;
    float acc = 0.0f;
    for (int k = lane; k < NH; k += 32) acc += hrow[k] * __ldg(&Ws[k]);
#pragma unroll
    for (int o = 16; o > 0; o >>= 1) acc += __shfl_down_sync(0xffffffffu, acc, o);
    if (lane == 0) g_scalar[b] = acc + bs[0];
}

// ---------------- per-row logsumexp + argmax + target logp (deterministic trees) ----------------
__global__ void __launch_bounds__(256) loss_row_kernel(const int* __restrict__ target) {
    __shared__ float sval[256];
    __shared__ int   sidx[256];
    __shared__ float ssum[256];
    const int b = blockIdx.x;
    const int tid = threadIdx.x;
    const float* row = g_logits + (size_t)b * NC;

    float mval = -3.402823466e38f;
    int midx = 0;
    for (int c = tid; c < NC; c += 256) {
        const float v = row[c];
        if (v > mval) { mval = v; midx = c; }
    }
    sval[tid] = mval; sidx[tid] = midx;
    __syncthreads();
    for (int s = 128; s > 0; s >>= 1) {
        if (tid < s) {
            const float v2 = sval[tid + s];
            const int   i2 = sidx[tid + s];
            if (v2 > sval[tid] || (v2 == sval[tid] && i2 < sidx[tid])) {
                sval[tid] = v2; sidx[tid] = i2;
            }
        }
        __syncthreads();
    }
    const float maxv = sval[0];
    const int   amax = sidx[0];

    float lsum = 0.0f;
    for (int c = tid; c < NC; c += 256) lsum += expf(row[c] - maxv);
    ssum[tid] = lsum;
    __syncthreads();
    for (int s = 128; s > 0; s >>= 1) {
        if (tid < s) ssum[tid] += ssum[tid + s];
        __syncthreads();
    }
    if (tid == 0) {
        const int t = target[b];
        g_row_lv[b]  = maxv + logf(ssum[0]) - row[t];
        g_row_acc[b] = (amax == t) ? 1.0f : 0.0f;
    }
}

// ---------------- final deterministic reduce -> 4 scalars ----------------
__global__ void __launch_bounds__(1024) final_kernel(const float* __restrict__ target_scalar,
                                                     float* __restrict__ out) {
    __shared__ float s_lv[1024];
    __shared__ float s_ac[1024];
    __shared__ float s_sq[1024];
    const int tid = threadIdx.x;
    float lv = 0.0f, ac = 0.0f, sq = 0.0f;
    for (int b = tid; b < NB; b += 1024) {
        lv += g_row_lv[b];
        ac += g_row_acc[b];
        const float d = g_scalar[b] - target_scalar[b];
        sq += d * d;
    }
    s_lv[tid] = lv; s_ac[tid] = ac; s_sq[tid] = sq;
    __syncthreads();
    for (int s = 512; s > 0; s >>= 1) {
        if (tid < s) {
            s_lv[tid] += s_lv[tid + s];
            s_ac[tid] += s_ac[tid + s];
            s_sq[tid] += s_sq[tid + s];
        }
        __syncthreads();
    }
    if (tid == 0) {
        const float lvm  = s_lv[0] / (float)NB;
        const float sqm  = s_sq[0] / (float)NB;
        const float accm = s_ac[0] / (float)NB;
        out[0] = lvm + sqm;   // total_loss
        out[1] = lvm;         // loss_vector
        out[2] = sqm;         // loss_scalar
        out[3] = accm;        // acc
    }
}

// ---------------- launch ----------------
extern "C" void kernel_launch(void* const* d_in, const int* in_sizes, int n_in,
                              void* d_out, int out_size) {
    const float* feature  = (const float*)d_in[0];
    const float* var_flat = (const float*)d_in[1];
    const int*   seg      = (const int*)d_in[2];
    const int*   target_v = (const int*)d_in[3];
    const float* target_s = (const float*)d_in[4];
    const float* Wv       = (const float*)d_in[5];
    const float* bv       = (const float*)d_in[6];
    const float* W1       = (const float*)d_in[7];
    const float* b1       = (const float*)d_in[8];
    const float* W2       = (const float*)d_in[9];
    const float* b2       = (const float*)d_in[10];
    const float* Ws       = (const float*)d_in[11];
    const float* bs       = (const float*)d_in[12];
    float* out = (float*)d_out;

    float *p_means, *p_comb, *p_hid, *p_log;
    cudaGetSymbolAddress((void**)&p_means, g_means);
    cudaGetSymbolAddress((void**)&p_comb,  g_combined);
    cudaGetSymbolAddress((void**)&p_hid,   g_hidden);
    cudaGetSymbolAddress((void**)&p_log,   g_logits);

    // 1) ragged per-segment mean
    seg_mean_kernel<<<NB, 256>>>(var_flat, seg);

    // 2) combined = means @ Wv^T + bv + feature     [4096 x 1024], K=32
    sgemm_nt<false, true><<<dim3(ND / 128, NB / 128), 256>>>(
        p_means, Wv, bv, feature, p_comb, NB, ND, NF);

    // 3) hidden = relu(combined @ W1^T + b1)        [4096 x 2048], K=1024
    sgemm_nt<true, false><<<dim3(NH / 128, NB / 128), 256>>>(
        p_comb, W1, b1, nullptr, p_hid, NB, NH, ND);

    // 4) logits = hidden @ W2^T + b2                [4096 x 1000], K=2048
    sgemm_nt<false, false><<<dim3((NC + 127) / 128, NB / 128), 256>>>(
        p_hid, W2, b2, nullptr, p_log, NB, NC, NH);

    // 5) scalar head
    scalar_kernel<<<NB / 8, 256>>>(Ws, bs);

    // 6) per-row softmax stats
    loss_row_kernel<<<NB, 256>>>(target_v);

    // 7) final reduce -> {total, lv, ls, acc}
    final_kernel<<<1, 1024>>>(target_s, out);
}

// round 4
// speedup vs baseline: 1.6384x; 1.6384x over previous
#include <cuda_runtime.h>
#include <math.h>
#include <stdint.h>

#define NB 4096
#define ND 1024
#define NH 2048
#define NC 1000
#define NT 819200
#define NF 32
#define NCPAD 1024

// ---------------- scratch (static device globals; no allocation) ----------------
__device__ float g_means[NB * NF];
__device__ float g_a1_hi[(size_t)NB * ND];      // combined, packed A-fragment layout (K=1024)
__device__ float g_a1_lo[(size_t)NB * ND];
__device__ float g_w1_hi[(size_t)NH * ND];      // W1, packed B-fragment layout
__device__ float g_w1_lo[(size_t)NH * ND];
__device__ float g_a2_hi[(size_t)NB * NH];      // hidden, packed A-fragment layout (K=2048)
__device__ float g_a2_lo[(size_t)NB * NH];
__device__ float g_w2_hi[(size_t)NCPAD * NH];   // W2 padded to 1024 rows, packed B layout
__device__ float g_w2_lo[(size_t)NCPAD * NH];
__device__ float g_hidden[(size_t)NB * NH];     // row-major (for scalar head)
__device__ float g_logits[(size_t)NB * NC];     // row-major
__device__ float g_scalar[NB];
__device__ float g_row_lv[NB];
__device__ float g_row_acc[NB];

// ---------------- helpers ----------------
__device__ __forceinline__ uint32_t smem_u32(const void* p) {
    uint32_t a;
    asm("{ .reg .u64 t; cvta.to.shared.u64 t, %1; cvt.u32.u64 %0, t; }" : "=r"(a) : "l"(p));
    return a;
}
__device__ __forceinline__ float to_tf32(float x) {
    uint32_t r;
    asm("cvt.rna.tf32.f32 %0, %1;" : "=r"(r) : "f"(x));
    return __uint_as_float(r);
}
__device__ __forceinline__ void cp16(uint32_t dst, const void* src) {
    asm volatile("cp.async.cg.shared.global [%0], [%1], 16;" :: "r"(dst), "l"(src) : "memory");
}
__device__ __forceinline__ void cp_commit() { asm volatile("cp.async.commit_group;" ::: "memory"); }

__device__ __forceinline__ void mma8(float* d, const uint32_t* a, const uint32_t* b) {
    asm volatile(
        "mma.sync.aligned.m16n8k8.row.col.f32.tf32.tf32.f32 "
        "{%0,%1,%2,%3}, {%4,%5,%6,%7}, {%8,%9}, {%0,%1,%2,%3};"
        : "+f"(d[0]), "+f"(d[1]), "+f"(d[2]), "+f"(d[3])
        : "r"(a[0]), "r"(a[1]), "r"(a[2]), "r"(a[3]), "r"(b[0]), "r"(b[1]));
}
__device__ __forceinline__ void lds128(uint32_t* r, uint32_t a) {
    asm volatile("ld.shared.v4.b32 {%0,%1,%2,%3}, [%4];"
                 : "=r"(r[0]), "=r"(r[1]), "=r"(r[2]), "=r"(r[3]) : "r"(a));
}
__device__ __forceinline__ void lds64(uint32_t* r, uint32_t a) {
    asm volatile("ld.shared.v2.b32 {%0,%1}, [%2];" : "=r"(r[0]), "=r"(r[1]) : "r"(a));
}

// packed A-fragment offset for element (r, c) of an M x K matrix (m16n8k8 A layout)
__device__ __forceinline__ size_t aoff(int r, int c, int K) {
    return ((size_t)((r >> 4) * (K >> 3) + (c >> 3)) * 32 + ((r & 7) << 2) + (c & 3)) * 4
           + ((r >> 3) & 1) + (((c >> 2) & 1) << 1);
}
// packed B-fragment offset for element (n, k) of an N x K matrix (m16n8k8 B layout)
__device__ __forceinline__ size_t boff(int n, int k, int K) {
    return ((size_t)((n >> 3) * (K >> 3) + (k >> 3)) * 32 + ((n & 7) << 2) + (k & 3)) * 2
           + ((k >> 2) & 1);
}

// ---------------- segment mean ----------------
__global__ void __launch_bounds__(256) seg_mean_kernel(const float* __restrict__ var_flat,
                                                       const int* __restrict__ seg) {
    __shared__ int s_bounds[2];
    __shared__ float red[8][32];
    const int b = blockIdx.x;
    const int tid = threadIdx.x;
    if (tid < 2) {
        const int v = b + tid;
        int lo = 0, hi = NT;
        while (lo < hi) {
            int mid = (lo + hi) >> 1;
            if (seg[mid] < v) lo = mid + 1; else hi = mid;
        }
        s_bounds[tid] = lo;
    }
    __syncthreads();
    const int start = s_bounds[0];
    const int end   = s_bounds[1];
    const int f = tid & 31;
    const int w = tid >> 5;
    float acc = 0.0f;
    for (int r = start + w; r < end; r += 8)
        acc += var_flat[(size_t)r * NF + f];
    red[w][f] = acc;
    __syncthreads();
    if (w == 0) {
        float s = 0.0f;
#pragma unroll
        for (int i = 0; i < 8; i++) s += red[i][f];
        const float cnt = fmaxf((float)(end - start), 1.0f);
        g_means[b * NF + f] = s / cnt;
    }
}

// ---------------- small fp32 NT GEMM (K=32): combined -> packed hi/lo ----------------
__global__ void __launch_bounds__(256, 2) sgemm_comb(const float* __restrict__ A,
                                                     const float* __restrict__ W,
                                                     const float* __restrict__ bias,
                                                     const float* __restrict__ addend,
                                                     float* __restrict__ Phi,
                                                     float* __restrict__ Plo,
                                                     int M, int N, int K) {
    __shared__ float As[8][128];
    __shared__ float Bs[8][128];
    const int bm  = blockIdx.y * 128;
    const int bn  = blockIdx.x * 128;
    const int tid = threadIdx.x;
    const int lrow = tid >> 1;
    const int lcol = (tid & 1) * 4;
    const int tx   = tid & 15;
    const int ty   = tid >> 4;
    float acc[8][8];
#pragma unroll
    for (int i = 0; i < 8; i++)
#pragma unroll
        for (int j = 0; j < 8; j++) acc[i][j] = 0.0f;
    const float* Ap = A + (size_t)(bm + lrow) * K + lcol;
    const float* Wp = W + (size_t)(bn + lrow) * K + lcol;
    for (int k0 = 0; k0 < K; k0 += 8) {
        const float4 av = *(const float4*)(Ap + k0);
        const float4 wv = *(const float4*)(Wp + k0);
        As[lcol + 0][lrow] = av.x; As[lcol + 1][lrow] = av.y;
        As[lcol + 2][lrow] = av.z; As[lcol + 3][lrow] = av.w;
        Bs[lcol + 0][lrow] = wv.x; Bs[lcol + 1][lrow] = wv.y;
        Bs[lcol + 2][lrow] = wv.z; Bs[lcol + 3][lrow] = wv.w;
        __syncthreads();
#pragma unroll
        for (int k = 0; k < 8; k++) {
            float a[8], bb[8];
#pragma unroll
            for (int i = 0; i < 8; i++) a[i] = As[k][ty * 8 + i];
#pragma unroll
            for (int j = 0; j < 8; j++) bb[j] = Bs[k][tx * 8 + j];
#pragma unroll
            for (int i = 0; i < 8; i++)
#pragma unroll
                for (int j = 0; j < 8; j++) acc[i][j] += a[i] * bb[j];
        }
        __syncthreads();
    }
#pragma unroll
    for (int i = 0; i < 8; i++) {
        const int m = bm + ty * 8 + i;
#pragma unroll
        for (int j = 0; j < 8; j++) {
            const int n = bn + tx * 8 + j;
            float v = acc[i][j] + bias[n] + addend[(size_t)m * N + n];
            const float hi = to_tf32(v);
            const size_t o = aoff(m, n, N);
            Phi[o] = hi;
            Plo[o] = to_tf32(v - hi);
        }
    }
}

// ---------------- weight split into packed B-fragment layout (rows padded) ----------------
__global__ void __launch_bounds__(256) split_b_kernel(const float* __restrict__ W,
                                                      float* __restrict__ hi,
                                                      float* __restrict__ lo,
                                                      int rows, int K, int prows) {
    const size_t idx = (size_t)blockIdx.x * 256 + threadIdx.x;
    const size_t tot = (size_t)prows * K;
    if (idx >= tot) return;
    const int n = (int)(idx / K);
    const int k = (int)(idx % K);
    const float v = (n < rows) ? W[idx] : 0.0f;
    const float h = to_tf32(v);
    const size_t o = boff(n, k, K);
    hi[o] = h;
    lo[o] = to_tf32(v - h);
}

// ---------------- tf32 3x tensor-core GEMM via mma.sync (NT), CTA 128x256, BK=32 ----------------
// Operands pre-packed in fragment order. 2-stage cp.async pipeline, 96KB/stage.
#define STAGE_BYTES 98304

#define LOADC(stg, ck) do {                                                         \
        const int _ck4 = (ck) * 4;                                                  \
        const uint32_t _dstS = sbase + (uint32_t)(stg) * (uint32_t)STAGE_BYTES;     \
        _Pragma("unroll")                                                           \
        for (int _i = 0; _i < 24; _i++) {                                           \
            const int _u = tid + _i * 256;                                          \
            const float* _src; uint32_t _dst;                                       \
            if (_u < 2048) {                                                        \
                const int _t = _u >> 10, _w = _u & 1023;                            \
                const int _mt = _w >> 7, _rem = _w & 127;                           \
                _src = (_t ? Alo : Ahi)                                             \
                     + ((size_t)(mtile0 + _mt) * KB8 + _ck4) * 128 + _rem * 4;      \
                _dst = _dstS + _t * 16384 + _w * 16;                                \
            } else {                                                                \
                const int _v = _u - 2048;                                           \
                const int _t = _v >> 11, _w = _v & 2047;                            \
                const int _nt = _w >> 6, _rem = _w & 63;                            \
                _src = (_t ? Blo : Bhi)                                             \
                     + ((size_t)(ntile0 + _nt) * KB8 + _ck4) * 64 + _rem * 4;       \
                _dst = _dstS + 32768 + _t * 32768 + _w * 16;                        \
            }                                                                       \
            cp16(_dst, _src);                                                       \
        }                                                                           \
        cp_commit();                                                                \
    } while (0)

template <int KDIM, bool IS_G1>
__global__ void __launch_bounds__(256, 1) mma_gemm(
    const float* __restrict__ Ahi, const float* __restrict__ Alo,
    const float* __restrict__ Bhi, const float* __restrict__ Blo,
    const float* __restrict__ bias,
    float* __restrict__ Crow, float* __restrict__ Phi, float* __restrict__ Plo) {
    constexpr int KB8 = KDIM / 8;
    constexpr int NCH = KDIM / 32;
    extern __shared__ __align__(16) char smem[];
    const int tid  = threadIdx.x;
    const int lane = tid & 31;
    const int wrp  = tid >> 5;
    const int warp_m = (wrp & 1) * 64;
    const int warp_n = (wrp >> 1) * 64;
    const int mtW = (wrp & 1) * 4;
    const int ntW = (wrp >> 1) * 8;
    const int bm = blockIdx.y * 128;
    const int bn = blockIdx.x * 256;
    const int mtile0 = blockIdx.y * 8;
    const int ntile0 = blockIdx.x * 32;
    const uint32_t sbase = smem_u32(smem);

    float acc[4][8][4];
#pragma unroll
    for (int a = 0; a < 4; a++)
#pragma unroll
        for (int b = 0; b < 8; b++)
#pragma unroll
            for (int c = 0; c < 4; c++) acc[a][b][c] = 0.0f;

    LOADC(0, 0);

#pragma unroll 1
    for (int ch = 0; ch < NCH; ch++) {
        if (ch + 1 < NCH) {
            LOADC((ch + 1) & 1, ch + 1);
            asm volatile("cp.async.wait_group 1;" ::: "memory");
        } else {
            asm volatile("cp.async.wait_group 0;" ::: "memory");
        }
        __syncthreads();
        const uint32_t stg = sbase + (uint32_t)(ch & 1) * (uint32_t)STAGE_BYTES;
#pragma unroll
        for (int kb = 0; kb < 4; kb++) {
            uint32_t ah[4][4], al[4][4];
#pragma unroll
            for (int mt = 0; mt < 4; mt++) {
                const uint32_t adr = stg + ((mtW + mt) * 4 + kb) * 512 + lane * 16;
                lds128(ah[mt], adr);
                lds128(al[mt], adr + 16384);
            }
#pragma unroll
            for (int nt = 0; nt < 8; nt++) {
                uint32_t bh[2], bl[2];
                const uint32_t badr = stg + 32768 + ((ntW + nt) * 4 + kb) * 256 + lane * 8;
                lds64(bh, badr);
                lds64(bl, badr + 32768);
#pragma unroll
                for (int mt = 0; mt < 4; mt++) {
                    mma8(acc[mt][nt], ah[mt], bh);
                    mma8(acc[mt][nt], ah[mt], bl);
                    mma8(acc[mt][nt], al[mt], bh);
                }
            }
        }
        __syncthreads();
    }

    // epilogue
    const int g  = lane >> 2;
    const int tg = lane & 3;
#pragma unroll
    for (int mt = 0; mt < 4; mt++) {
#pragma unroll
        for (int nt = 0; nt < 8; nt++) {
#pragma unroll
            for (int r = 0; r < 4; r++) {
                const int row = bm + warp_m + mt * 16 + g + ((r >> 1) << 3);
                const int col = bn + warp_n + nt * 8 + tg * 2 + (r & 1);
                float v = acc[mt][nt][r];
                if (IS_G1) {
                    v += __ldg(&bias[col]);
                    v = fmaxf(v, 0.0f);
                    Crow[(size_t)row * NH + col] = v;
                    const float h = to_tf32(v);
                    const size_t o = aoff(row, col, NH);
                    Phi[o] = h;
                    Plo[o] = to_tf32(v - h);
                } else {
                    if (col < NC) {
                        v += __ldg(&bias[col]);
                        Crow[(size_t)row * NC + col] = v;
                    }
                }
            }
        }
    }
}

// ---------------- scalar head ----------------
__global__ void __launch_bounds__(256) scalar_kernel(const float* __restrict__ Ws,
                                                     const float* __restrict__ bs) {
    const int warp = threadIdx.x >> 5;
    const int lane = threadIdx.x & 31;
    const int b = blockIdx.x * 8 + warp;
    const float* hrow = g_hidden + (size_t)b * NH;
    float acc = 0.0f;
    for (int k = lane; k < NH; k += 32) acc += hrow[k] * __ldg(&Ws[k]);
#pragma unroll
    for (int o = 16; o > 0; o >>= 1) acc += __shfl_down_sync(0xffffffffu, acc, o);
    if (lane == 0) g_scalar[b] = acc + bs[0];
}

// ---------------- per-row logsumexp + argmax ----------------
__global__ void __launch_bounds__(256) loss_row_kernel(const int* __restrict__ target) {
    __shared__ float sval[256];
    __shared__ int   sidx[256];
    __shared__ float ssum[256];
    const int b = blockIdx.x;
    const int tid = threadIdx.x;
    const float* row = g_logits + (size_t)b * NC;

    float mval = -3.402823466e38f;
    int midx = 0;
    for (int c = tid; c < NC; c += 256) {
        const float v = row[c];
        if (v > mval) { mval = v; midx = c; }
    }
    sval[tid] = mval; sidx[tid] = midx;
    __syncthreads();
    for (int s = 128; s > 0; s >>= 1) {
        if (tid < s) {
            const float v2 = sval[tid + s];
            const int   i2 = sidx[tid + s];
            if (v2 > sval[tid] || (v2 == sval[tid] && i2 < sidx[tid])) {
                sval[tid] = v2; sidx[tid] = i2;
            }
        }
        __syncthreads();
    }
    const float maxv = sval[0];
    const int   amax = sidx[0];

    float lsum = 0.0f;
    for (int c = tid; c < NC; c += 256) lsum += expf(row[c] - maxv);
    ssum[tid] = lsum;
    __syncthreads();
    for (int s = 128; s > 0; s >>= 1) {
        if (tid < s) ssum[tid] += ssum[tid + s];
        __syncthreads();
    }
    if (tid == 0) {
        const int t = target[b];
        g_row_lv[b]  = maxv + logf(ssum[0]) - row[t];
        g_row_acc[b] = (amax == t) ? 1.0f : 0.0f;
    }
}

// ---------------- final reduce ----------------
__global__ void __launch_bounds__(1024) final_kernel(const float* __restrict__ target_scalar,
                                                     float* __restrict__ out) {
    __shared__ float s_lv[1024];
    __shared__ float s_ac[1024];
    __shared__ float s_sq[1024];
    const int tid = threadIdx.x;
    float lv = 0.0f, ac = 0.0f, sq = 0.0f;
    for (int b = tid; b < NB; b += 1024) {
        lv += g_row_lv[b];
        ac += g_row_acc[b];
        const float d = g_scalar[b] - target_scalar[b];
        sq += d * d;
    }
    s_lv[tid] = lv; s_ac[tid] = ac; s_sq[tid] = sq;
    __syncthreads();
    for (int s = 512; s > 0; s >>= 1) {
        if (tid < s) {
            s_lv[tid] += s_lv[tid + s];
            s_ac[tid] += s_ac[tid + s];
            s_sq[tid] += s_sq[tid + s];
        }
        __syncthreads();
    }
    if (tid == 0) {
        const float lvm  = s_lv[0] / (float)NB;
        const float sqm  = s_sq[0] / (float)NB;
        const float accm = s_ac[0] / (float)NB;
        out[0] = lvm + sqm;
        out[1] = lvm;
        out[2] = sqm;
        out[3] = accm;
    }
}

// ---------------- launch ----------------
extern "C" void kernel_launch(void* const* d_in, const int* in_sizes, int n_in,
                              void* d_out, int out_size) {
    const float* feature  = (const float*)d_in[0];
    const float* var_flat = (const float*)d_in[1];
    const int*   seg      = (const int*)d_in[2];
    const int*   target_v = (const int*)d_in[3];
    const float* target_s = (const float*)d_in[4];
    const float* Wv       = (const float*)d_in[5];
    const float* bv       = (const float*)d_in[6];
    const float* W1       = (const float*)d_in[7];
    const float* b1       = (const float*)d_in[8];
    const float* W2       = (const float*)d_in[9];
    const float* b2       = (const float*)d_in[10];
    const float* Ws       = (const float*)d_in[11];
    const float* bs       = (const float*)d_in[12];
    float* out = (float*)d_out;

    float *p_means, *p_a1h, *p_a1l, *p_w1h, *p_w1l, *p_a2h, *p_a2l, *p_w2h, *p_w2l;
    float *p_hid, *p_log;
    cudaGetSymbolAddress((void**)&p_means, g_means);
    cudaGetSymbolAddress((void**)&p_a1h,   g_a1_hi);
    cudaGetSymbolAddress((void**)&p_a1l,   g_a1_lo);
    cudaGetSymbolAddress((void**)&p_w1h,   g_w1_hi);
    cudaGetSymbolAddress((void**)&p_w1l,   g_w1_lo);
    cudaGetSymbolAddress((void**)&p_a2h,   g_a2_hi);
    cudaGetSymbolAddress((void**)&p_a2l,   g_a2_lo);
    cudaGetSymbolAddress((void**)&p_w2h,   g_w2_hi);
    cudaGetSymbolAddress((void**)&p_w2l,   g_w2_lo);
    cudaGetSymbolAddress((void**)&p_hid,   g_hidden);
    cudaGetSymbolAddress((void**)&p_log,   g_logits);

    const int SMEM_GEMM = 2 * STAGE_BYTES;  // 196608
    cudaFuncSetAttribute(mma_gemm<1024, true>,
                         cudaFuncAttributeMaxDynamicSharedMemorySize, SMEM_GEMM);
    cudaFuncSetAttribute(mma_gemm<2048, false>,
                         cudaFuncAttributeMaxDynamicSharedMemorySize, SMEM_GEMM);

    // 1) ragged per-segment mean
    seg_mean_kernel<<<NB, 256>>>(var_flat, seg);

    // 2) weight splits into packed B-fragment layout
    {
        size_t n1 = (size_t)NH * ND;
        split_b_kernel<<<(int)((n1 + 255) / 256), 256>>>(W1, p_w1h, p_w1l, NH, ND, NH);
        size_t n2 = (size_t)NCPAD * NH;
        split_b_kernel<<<(int)((n2 + 255) / 256), 256>>>(W2, p_w2h, p_w2l, NC, NH, NCPAD);
    }

    // 3) combined = means@Wv^T + bv + feature -> packed A hi/lo
    sgemm_comb<<<dim3(ND / 128, NB / 128), 256>>>(
        p_means, Wv, bv, feature, p_a1h, p_a1l, NB, ND, NF);

    // 4) hidden = relu(combined@W1^T + b1)  [mma.sync tf32 3x]
    mma_gemm<1024, true><<<dim3(NH / 256, NB / 128), 256, SMEM_GEMM>>>(
        p_a1h, p_a1l, p_w1h, p_w1l, b1, p_hid, p_a2h, p_a2l);

    // 5) logits = hidden@W2^T + b2  [mma.sync tf32 3x], N guard 1000
    mma_gemm<2048, false><<<dim3(NCPAD / 256, NB / 128), 256, SMEM_GEMM>>>(
        p_a2h, p_a2l, p_w2h, p_w2l, b2, p_log, nullptr, nullptr);

    // 6) scalar head
    scalar_kernel<<<NB / 8, 256>>>(Ws, bs);

    // 7) per-row softmax stats
    loss_row_kernel<<<NB, 256>>>(target_v);

    // 8) final reduce
    final_kernel<<<1, 1024>>>(target_s, out);
}

// round 5
// speedup vs baseline: 2.8158x; 1.7187x over previous
#include <cuda_runtime.h>
#include <cuda_fp16.h>
#include <math.h>
#include <stdint.h>

#define NB 4096
#define ND 1024
#define NH 2048
#define NC 1000
#define NT 819200
#define NF 32
#define NCPAD 1024

// ---------------- scratch (static device globals; no allocation) ----------------
__device__ float  g_means[NB * NF];
__device__ __half g_a1_hi[(size_t)NB * ND];      // combined, packed A-fragment fp16 (K=1024)
__device__ __half g_a1_lo[(size_t)NB * ND];
__device__ __half g_w1_hi[(size_t)NH * ND];      // W1, packed B-fragment fp16
__device__ __half g_w1_lo[(size_t)NH * ND];
__device__ __half g_a2_hi[(size_t)NB * NH];      // hidden, packed A-fragment fp16 (K=2048)
__device__ __half g_a2_lo[(size_t)NB * NH];
__device__ __half g_w2_hi[(size_t)NCPAD * NH];   // W2 padded, packed B-fragment fp16
__device__ __half g_w2_lo[(size_t)NCPAD * NH];
__device__ float  g_hidden[(size_t)NB * NH];     // row-major fp32 (scalar head)
__device__ float  g_logits[(size_t)NB * NC];
__device__ float  g_scalar[NB];
__device__ float  g_row_lv[NB];
__device__ float  g_row_acc[NB];

// ---------------- helpers ----------------
__device__ __forceinline__ uint32_t smem_u32(const void* p) {
    uint32_t a;
    asm("{ .reg .u64 t; cvta.to.shared.u64 t, %1; cvt.u32.u64 %0, t; }" : "=r"(a) : "l"(p));
    return a;
}
__device__ __forceinline__ void cp16(uint32_t dst, const void* src) {
    asm volatile("cp.async.cg.shared.global [%0], [%1], 16;" :: "r"(dst), "l"(src) : "memory");
}
__device__ __forceinline__ void cp_commit() { asm volatile("cp.async.commit_group;" ::: "memory"); }

__device__ __forceinline__ void mma16(float* d, const uint32_t* a, const uint32_t* b) {
    asm volatile(
        "mma.sync.aligned.m16n8k16.row.col.f32.f16.f16.f32 "
        "{%0,%1,%2,%3}, {%4,%5,%6,%7}, {%8,%9}, {%0,%1,%2,%3};"
        : "+f"(d[0]), "+f"(d[1]), "+f"(d[2]), "+f"(d[3])
        : "r"(a[0]), "r"(a[1]), "r"(a[2]), "r"(a[3]), "r"(b[0]), "r"(b[1]));
}
__device__ __forceinline__ void lds128(uint32_t* r, uint32_t a) {
    asm volatile("ld.shared.v4.b32 {%0,%1,%2,%3}, [%4];"
                 : "=r"(r[0]), "=r"(r[1]), "=r"(r[2]), "=r"(r[3]) : "r"(a));
}
__device__ __forceinline__ void lds64(uint32_t* r, uint32_t a) {
    asm volatile("ld.shared.v2.b32 {%0,%1}, [%2];" : "=r"(r[0]), "=r"(r[1]) : "r"(a));
}

// packed fp16 A-fragment offset (m16n8k16) for element (r, c) of M x K: fp16 units
__device__ __forceinline__ size_t aoff16(int r, int c, int K) {
    const size_t tile = (size_t)(r >> 4) * (K >> 4) + (c >> 4);
    const int lane = ((r & 7) << 2) + ((c >> 1) & 3);
    const int reg  = ((r >> 3) & 1) + (((c >> 3) & 1) << 1);
    return tile * 256 + (size_t)((lane << 2) + reg) * 2 + (c & 1);
}
// packed fp16 B-fragment offset (m16n8k16) for element (n, k) of N x K
__device__ __forceinline__ size_t boff16(int n, int k, int K) {
    const size_t tile = (size_t)(n >> 3) * (K >> 4) + (k >> 4);
    const int lane = ((n & 7) << 2) + ((k >> 1) & 3);
    const int reg  = (k >> 3) & 1;
    return tile * 128 + (size_t)((lane << 1) + reg) * 2 + (k & 1);
}
__device__ __forceinline__ __half2 split_pair(float v0, float v1, __half2& lo) {
    const __half h0 = __float2half_rn(v0);
    const __half h1 = __float2half_rn(v1);
    lo = __halves2half2(__float2half_rn(v0 - __half2float(h0)),
                        __float2half_rn(v1 - __half2float(h1)));
    return __halves2half2(h0, h1);
}

// ---------------- segment mean ----------------
__global__ void __launch_bounds__(256) seg_mean_kernel(const float* __restrict__ var_flat,
                                                       const int* __restrict__ seg) {
    __shared__ int s_bounds[2];
    __shared__ float red[8][32];
    const int b = blockIdx.x;
    const int tid = threadIdx.x;
    if (tid < 2) {
        const int v = b + tid;
        int lo = 0, hi = NT;
        while (lo < hi) {
            int mid = (lo + hi) >> 1;
            if (seg[mid] < v) lo = mid + 1; else hi = mid;
        }
        s_bounds[tid] = lo;
    }
    __syncthreads();
    const int start = s_bounds[0];
    const int end   = s_bounds[1];
    const int f = tid & 31;
    const int w = tid >> 5;
    float acc = 0.0f;
    for (int r = start + w; r < end; r += 8)
        acc += var_flat[(size_t)r * NF + f];
    red[w][f] = acc;
    __syncthreads();
    if (w == 0) {
        float s = 0.0f;
#pragma unroll
        for (int i = 0; i < 8; i++) s += red[i][f];
        const float cnt = fmaxf((float)(end - start), 1.0f);
        g_means[b * NF + f] = s / cnt;
    }
}

// ---------------- small fp32 NT GEMM (K=32): combined -> packed fp16 hi/lo ----------------
__global__ void __launch_bounds__(256, 2) sgemm_comb(const float* __restrict__ A,
                                                     const float* __restrict__ W,
                                                     const float* __restrict__ bias,
                                                     const float* __restrict__ addend,
                                                     __half* __restrict__ Phi,
                                                     __half* __restrict__ Plo,
                                                     int M, int N, int K) {
    __shared__ float As[8][128];
    __shared__ float Bs[8][128];
    const int bm  = blockIdx.y * 128;
    const int bn  = blockIdx.x * 128;
    const int tid = threadIdx.x;
    const int lrow = tid >> 1;
    const int lcol = (tid & 1) * 4;
    const int tx   = tid & 15;
    const int ty   = tid >> 4;
    float acc[8][8];
#pragma unroll
    for (int i = 0; i < 8; i++)
#pragma unroll
        for (int j = 0; j < 8; j++) acc[i][j] = 0.0f;
    const float* Ap = A + (size_t)(bm + lrow) * K + lcol;
    const float* Wp = W + (size_t)(bn + lrow) * K + lcol;
    for (int k0 = 0; k0 < K; k0 += 8) {
        const float4 av = *(const float4*)(Ap + k0);
        const float4 wv = *(const float4*)(Wp + k0);
        As[lcol + 0][lrow] = av.x; As[lcol + 1][lrow] = av.y;
        As[lcol + 2][lrow] = av.z; As[lcol + 3][lrow] = av.w;
        Bs[lcol + 0][lrow] = wv.x; Bs[lcol + 1][lrow] = wv.y;
        Bs[lcol + 2][lrow] = wv.z; Bs[lcol + 3][lrow] = wv.w;
        __syncthreads();
#pragma unroll
        for (int k = 0; k < 8; k++) {
            float a[8], bb[8];
#pragma unroll
            for (int i = 0; i < 8; i++) a[i] = As[k][ty * 8 + i];
#pragma unroll
            for (int j = 0; j < 8; j++) bb[j] = Bs[k][tx * 8 + j];
#pragma unroll
            for (int i = 0; i < 8; i++)
#pragma unroll
                for (int j = 0; j < 8; j++) acc[i][j] += a[i] * bb[j];
        }
        __syncthreads();
    }
#pragma unroll
    for (int i = 0; i < 8; i++) {
        const int m = bm + ty * 8 + i;
#pragma unroll
        for (int j = 0; j < 8; j += 2) {
            const int n = bn + tx * 8 + j;
            const float v0 = acc[i][j]     + bias[n]     + addend[(size_t)m * N + n];
            const float v1 = acc[i][j + 1] + bias[n + 1] + addend[(size_t)m * N + n + 1];
            __half2 lo;
            const __half2 hi = split_pair(v0, v1, lo);
            const size_t o = aoff16(m, n, N) >> 1;
            ((__half2*)Phi)[o] = hi;
            ((__half2*)Plo)[o] = lo;
        }
    }
}

// ---------------- weight split into packed fp16 B-fragment layout (rows padded) ----------------
__global__ void __launch_bounds__(256) split_b_kernel(const float* __restrict__ W,
                                                      __half* __restrict__ hi,
                                                      __half* __restrict__ lo,
                                                      int rows, int K, int prows) {
    const size_t idx = (size_t)blockIdx.x * 256 + threadIdx.x;
    const size_t tot = (size_t)prows * (K >> 1);
    if (idx >= tot) return;
    const int n = (int)(idx / (K >> 1));
    const int k = (int)(idx % (K >> 1)) * 2;
    float v0 = 0.0f, v1 = 0.0f;
    if (n < rows) {
        v0 = W[(size_t)n * K + k];
        v1 = W[(size_t)n * K + k + 1];
    }
    __half2 l;
    const __half2 h = split_pair(v0, v1, l);
    const size_t o = boff16(n, k, K) >> 1;
    ((__half2*)hi)[o] = h;
    ((__half2*)lo)[o] = l;
}

// ---------------- fp16 2-split tensor-core GEMM (NT), CTA 128x256, BK=32, 3-stage ----------------
#define STAGE_BYTES 49152

#define LOADC(stg, ck) do {                                                          \
        const uint32_t _d0 = sbase + (uint32_t)(stg) * (uint32_t)STAGE_BYTES;        \
        _Pragma("unroll")                                                            \
        for (int _i = 0; _i < 12; _i++) {                                            \
            const int _u = tid + _i * 256;                                           \
            const __half* _src; uint32_t _dst;                                       \
            if (_u < 1024) {                                                         \
                const int _t = _u >> 9, _w = _u & 511;                               \
                const int _mt = _w >> 6, _rem = _w & 63;                             \
                _src = (_t ? Alo : Ahi)                                              \
                     + ((size_t)(mtile0 + _mt) * KB16 + 2 * (ck)) * 256 + _rem * 8;  \
                _dst = _d0 + _t * 8192 + _mt * 1024 + _rem * 16;                     \
            } else {                                                                 \
                const int _v = _u - 1024;                                            \
                const int _t = _v >> 10, _w = _v & 1023;                             \
                const int _nt = _w >> 5, _rem = _w & 31;                             \
                _src = (_t ? Blo : Bhi)                                              \
                     + ((size_t)(ntile0 + _nt) * KB16 + 2 * (ck)) * 128 + _rem * 8;  \
                _dst = _d0 + 16384 + _t * 16384 + _nt * 512 + _rem * 16;             \
            }                                                                        \
            cp16(_dst, _src);                                                        \
        }                                                                            \
        cp_commit();                                                                 \
    } while (0)

template <int KDIM, bool IS_G1>
__global__ void __launch_bounds__(256, 1) mma_gemm(
    const __half* __restrict__ Ahi, const __half* __restrict__ Alo,
    const __half* __restrict__ Bhi, const __half* __restrict__ Blo,
    const float* __restrict__ bias,
    float* __restrict__ Crow, __half* __restrict__ Phi, __half* __restrict__ Plo) {
    constexpr int KB16 = KDIM / 16;
    constexpr int NCH  = KDIM / 32;
    extern __shared__ __align__(16) char smem[];
    const int tid  = threadIdx.x;
    const int lane = tid & 31;
    const int wrp  = tid >> 5;
    const int warp_m = (wrp & 1) * 64;
    const int warp_n = (wrp >> 1) * 64;
    const int mtW = (wrp & 1) * 4;
    const int ntW = (wrp >> 1) * 8;
    const int bm = blockIdx.y * 128;
    const int bn = blockIdx.x * 256;
    const int mtile0 = blockIdx.y * 8;
    const int ntile0 = blockIdx.x * 32;
    const uint32_t sbase = smem_u32(smem);

    float acc[4][8][4];
#pragma unroll
    for (int a = 0; a < 4; a++)
#pragma unroll
        for (int b = 0; b < 8; b++)
#pragma unroll
            for (int c = 0; c < 4; c++) acc[a][b][c] = 0.0f;

    LOADC(0, 0);
    LOADC(1, 1);

#pragma unroll 1
    for (int ch = 0; ch < NCH; ch++) {
        if (ch + 2 < NCH) {
            LOADC((ch + 2) % 3, ch + 2);
            asm volatile("cp.async.wait_group 2;" ::: "memory");
        } else if (ch + 1 < NCH) {
            asm volatile("cp.async.wait_group 1;" ::: "memory");
        } else {
            asm volatile("cp.async.wait_group 0;" ::: "memory");
        }
        __syncthreads();
        const uint32_t stg = sbase + (uint32_t)(ch % 3) * (uint32_t)STAGE_BYTES;
#pragma unroll
        for (int kt = 0; kt < 2; kt++) {
            uint32_t ah[4][4], al[4][4];
#pragma unroll
            for (int mt = 0; mt < 4; mt++) {
                const uint32_t adr = stg + (mtW + mt) * 1024 + kt * 512 + lane * 16;
                lds128(ah[mt], adr);
                lds128(al[mt], adr + 8192);
            }
#pragma unroll
            for (int nt = 0; nt < 8; nt++) {
                uint32_t bh[2], bl[2];
                const uint32_t badr = stg + 16384 + (ntW + nt) * 512 + kt * 256 + lane * 8;
                lds64(bh, badr);
                lds64(bl, badr + 16384);
#pragma unroll
                for (int mt = 0; mt < 4; mt++) {
                    mma16(acc[mt][nt], ah[mt], bh);
                    mma16(acc[mt][nt], ah[mt], bl);
                    mma16(acc[mt][nt], al[mt], bh);
                }
            }
        }
        __syncthreads();
    }

    // epilogue
    const int g  = lane >> 2;
    const int tg = lane & 3;
#pragma unroll
    for (int mt = 0; mt < 4; mt++) {
#pragma unroll
        for (int nt = 0; nt < 8; nt++) {
            const int col0 = bn + warp_n + nt * 8 + tg * 2;
            const int row0 = bm + warp_m + mt * 16 + g;
#pragma unroll
            for (int half = 0; half < 2; half++) {
                const int row = row0 + half * 8;
                float v0 = acc[mt][nt][half * 2 + 0];
                float v1 = acc[mt][nt][half * 2 + 1];
                if (IS_G1) {
                    v0 = fmaxf(v0 + __ldg(&bias[col0]), 0.0f);
                    v1 = fmaxf(v1 + __ldg(&bias[col0 + 1]), 0.0f);
                    Crow[(size_t)row * NH + col0]     = v0;
                    Crow[(size_t)row * NH + col0 + 1] = v1;
                    __half2 lo;
                    const __half2 hi = split_pair(v0, v1, lo);
                    const size_t o = aoff16(row, col0, NH) >> 1;
                    ((__half2*)Phi)[o] = hi;
                    ((__half2*)Plo)[o] = lo;
                } else {
                    if (col0 < NC)
                        Crow[(size_t)row * NC + col0] = v0 + __ldg(&bias[col0]);
                    if (col0 + 1 < NC)
                        Crow[(size_t)row * NC + col0 + 1] = v1 + __ldg(&bias[col0 + 1]);
                }
            }
        }
    }
}

// ---------------- scalar head ----------------
__global__ void __launch_bounds__(256) scalar_kernel(const float* __restrict__ Ws,
                                                     const float* __restrict__ bs) {
    const int warp = threadIdx.x >> 5;
    const int lane = threadIdx.x & 31;
    const int b = blockIdx.x * 8 + warp;
    const float* hrow = g_hidden + (size_t)b * NH;
    float acc = 0.0f;
    for (int k = lane; k < NH; k += 32) acc += hrow[k] * __ldg(&Ws[k]);
#pragma unroll
    for (int o = 16; o > 0; o >>= 1) acc += __shfl_down_sync(0xffffffffu, acc, o);
    if (lane == 0) g_scalar[b] = acc + bs[0];
}

// ---------------- per-row logsumexp + argmax ----------------
__global__ void __launch_bounds__(256) loss_row_kernel(const int* __restrict__ target) {
    __shared__ float sval[256];
    __shared__ int   sidx[256];
    __shared__ float ssum[256];
    const int b = blockIdx.x;
    const int tid = threadIdx.x;
    const float* row = g_logits + (size_t)b * NC;

    float mval = -3.402823466e38f;
    int midx = 0;
    for (int c = tid; c < NC; c += 256) {
        const float v = row[c];
        if (v > mval) { mval = v; midx = c; }
    }
    sval[tid] = mval; sidx[tid] = midx;
    __syncthreads();
    for (int s = 128; s > 0; s >>= 1) {
        if (tid < s) {
            const float v2 = sval[tid + s];
            const int   i2 = sidx[tid + s];
            if (v2 > sval[tid] || (v2 == sval[tid] && i2 < sidx[tid])) {
                sval[tid] = v2; sidx[tid] = i2;
            }
        }
        __syncthreads();
    }
    const float maxv = sval[0];
    const int   amax = sidx[0];

    float lsum = 0.0f;
    for (int c = tid; c < NC; c += 256) lsum += expf(row[c] - maxv);
    ssum[tid] = lsum;
    __syncthreads();
    for (int s = 128; s > 0; s >>= 1) {
        if (tid < s) ssum[tid] += ssum[tid + s];
        __syncthreads();
    }
    if (tid == 0) {
        const int t = target[b];
        g_row_lv[b]  = maxv + logf(ssum[0]) - row[t];
        g_row_acc[b] = (amax == t) ? 1.0f : 0.0f;
    }
}

// ---------------- final reduce ----------------
__global__ void __launch_bounds__(1024) final_kernel(const float* __restrict__ target_scalar,
                                                     float* __restrict__ out) {
    __shared__ float s_lv[1024];
    __shared__ float s_ac[1024];
    __shared__ float s_sq[1024];
    const int tid = threadIdx.x;
    float lv = 0.0f, ac = 0.0f, sq = 0.0f;
    for (int b = tid; b < NB; b += 1024) {
        lv += g_row_lv[b];
        ac += g_row_acc[b];
        const float d = g_scalar[b] - target_scalar[b];
        sq += d * d;
    }
    s_lv[tid] = lv; s_ac[tid] = ac; s_sq[tid] = sq;
    __syncthreads();
    for (int s = 512; s > 0; s >>= 1) {
        if (tid < s) {
            s_lv[tid] += s_lv[tid + s];
            s_ac[tid] += s_ac[tid + s];
            s_sq[tid] += s_sq[tid + s];
        }
        __syncthreads();
    }
    if (tid == 0) {
        const float lvm  = s_lv[0] / (float)NB;
        const float sqm  = s_sq[0] / (float)NB;
        const float accm = s_ac[0] / (float)NB;
        out[0] = lvm + sqm;
        out[1] = lvm;
        out[2] = sqm;
        out[3] = accm;
    }
}

// ---------------- launch ----------------
extern "C" void kernel_launch(void* const* d_in, const int* in_sizes, int n_in,
                              void* d_out, int out_size) {
    const float* feature  = (const float*)d_in[0];
    const float* var_flat = (const float*)d_in[1];
    const int*   seg      = (const int*)d_in[2];
    const int*   target_v = (const int*)d_in[3];
    const float* target_s = (const float*)d_in[4];
    const float* Wv       = (const float*)d_in[5];
    const float* bv       = (const float*)d_in[6];
    const float* W1       = (const float*)d_in[7];
    const float* b1       = (const float*)d_in[8];
    const float* W2       = (const float*)d_in[9];
    const float* b2       = (const float*)d_in[10];
    const float* Ws       = (const float*)d_in[11];
    const float* bs       = (const float*)d_in[12];
    float* out = (float*)d_out;

    float *p_means, *p_hid, *p_log;
    __half *p_a1h, *p_a1l, *p_w1h, *p_w1l, *p_a2h, *p_a2l, *p_w2h, *p_w2l;
    cudaGetSymbolAddress((void**)&p_means, g_means);
    cudaGetSymbolAddress((void**)&p_a1h,   g_a1_hi);
    cudaGetSymbolAddress((void**)&p_a1l,   g_a1_lo);
    cudaGetSymbolAddress((void**)&p_w1h,   g_w1_hi);
    cudaGetSymbolAddress((void**)&p_w1l,   g_w1_lo);
    cudaGetSymbolAddress((void**)&p_a2h,   g_a2_hi);
    cudaGetSymbolAddress((void**)&p_a2l,   g_a2_lo);
    cudaGetSymbolAddress((void**)&p_w2h,   g_w2_hi);
    cudaGetSymbolAddress((void**)&p_w2l,   g_w2_lo);
    cudaGetSymbolAddress((void**)&p_hid,   g_hidden);
    cudaGetSymbolAddress((void**)&p_log,   g_logits);

    const int SMEM_GEMM = 3 * STAGE_BYTES;  // 147456
    cudaFuncSetAttribute(mma_gemm<1024, true>,
                         cudaFuncAttributeMaxDynamicSharedMemorySize, SMEM_GEMM);
    cudaFuncSetAttribute(mma_gemm<2048, false>,
                         cudaFuncAttributeMaxDynamicSharedMemorySize, SMEM_GEMM);

    // 1) ragged per-segment mean
    seg_mean_kernel<<<NB, 256>>>(var_flat, seg);

    // 2) weight splits into packed fp16 B-fragment layout
    {
        size_t n1 = (size_t)NH * ND / 2;
        split_b_kernel<<<(int)((n1 + 255) / 256), 256>>>(W1, p_w1h, p_w1l, NH, ND, NH);
        size_t n2 = (size_t)NCPAD * NH / 2;
        split_b_kernel<<<(int)((n2 + 255) / 256), 256>>>(W2, p_w2h, p_w2l, NC, NH, NCPAD);
    }

    // 3) combined = means@Wv^T + bv + feature -> packed fp16 A hi/lo
    sgemm_comb<<<dim3(ND / 128, NB / 128), 256>>>(
        p_means, Wv, bv, feature, p_a1h, p_a1l, NB, ND, NF);

    // 4) hidden = relu(combined@W1^T + b1)  [mma.sync fp16 2-split]
    mma_gemm<1024, true><<<dim3(NH / 256, NB / 128), 256, SMEM_GEMM>>>(
        p_a1h, p_a1l, p_w1h, p_w1l, b1, p_hid, p_a2h, p_a2l);

    // 5) logits = hidden@W2^T + b2  [mma.sync fp16 2-split], N guard 1000
    mma_gemm<2048, false><<<dim3(NCPAD / 256, NB / 128), 256, SMEM_GEMM>>>(
        p_a2h, p_a2l, p_w2h, p_w2l, b2, p_log, nullptr, nullptr);

    // 6) scalar head
    scalar_kernel<<<NB / 8, 256>>>(Ws, bs);

    // 7) per-row softmax stats
    loss_row_kernel<<<NB, 256>>>(target_v);

    // 8) final reduce
    final_kernel<<<1, 1024>>>(target_s, out);
}

// round 6
// speedup vs baseline: 2.8408x; 1.0089x over previous
#include <cuda_runtime.h>
#include <cuda_fp16.h>
#include <math.h>
#include <stdint.h>

#define NB 4096
#define ND 1024
#define NH 2048
#define NC 1000
#define NT 819200
#define NF 32
#define NCPAD 1024

// ---------------- scratch (static device globals; no allocation) ----------------
__device__ float  g_means[NB * NF];
__device__ __half g_a1_hi[(size_t)NB * ND];
__device__ __half g_a1_lo[(size_t)NB * ND];
__device__ __half g_w1_hi[(size_t)NH * ND];
__device__ __half g_w1_lo[(size_t)NH * ND];
__device__ __half g_a2_hi[(size_t)NB * NH];
__device__ __half g_a2_lo[(size_t)NB * NH];
__device__ __half g_w2_hi[(size_t)NCPAD * NH];
__device__ __half g_w2_lo[(size_t)NCPAD * NH];
__device__ float  g_hidden[(size_t)NB * NH];
__device__ float  g_logits[(size_t)NB * NC];
__device__ float  g_scalar[NB];
__device__ float  g_row_lv[NB];
__device__ float  g_row_acc[NB];

// ---------------- helpers ----------------
__device__ __forceinline__ uint32_t smem_u32(const void* p) {
    uint32_t a;
    asm("{ .reg .u64 t; cvta.to.shared.u64 t, %1; cvt.u32.u64 %0, t; }" : "=r"(a) : "l"(p));
    return a;
}
__device__ __forceinline__ void cp16(uint32_t dst, const void* src) {
    asm volatile("cp.async.cg.shared.global [%0], [%1], 16;" :: "r"(dst), "l"(src) : "memory");
}
__device__ __forceinline__ void cp_commit() { asm volatile("cp.async.commit_group;" ::: "memory"); }

__device__ __forceinline__ void mma16(float* d, const uint32_t* a, const uint32_t* b) {
    asm volatile(
        "mma.sync.aligned.m16n8k16.row.col.f32.f16.f16.f32 "
        "{%0,%1,%2,%3}, {%4,%5,%6,%7}, {%8,%9}, {%0,%1,%2,%3};"
        : "+f"(d[0]), "+f"(d[1]), "+f"(d[2]), "+f"(d[3])
        : "r"(a[0]), "r"(a[1]), "r"(a[2]), "r"(a[3]), "r"(b[0]), "r"(b[1]));
}
__device__ __forceinline__ void lds128(uint32_t* r, uint32_t a) {
    asm volatile("ld.shared.v4.b32 {%0,%1,%2,%3}, [%4];"
                 : "=r"(r[0]), "=r"(r[1]), "=r"(r[2]), "=r"(r[3]) : "r"(a));
}
__device__ __forceinline__ void lds64(uint32_t* r, uint32_t a) {
    asm volatile("ld.shared.v2.b32 {%0,%1}, [%2];" : "=r"(r[0]), "=r"(r[1]) : "r"(a));
}

// packed fp16 A-fragment offset (m16n8k16) for element (r, c) of M x K: fp16 units
__device__ __forceinline__ size_t aoff16(int r, int c, int K) {
    const size_t tile = (size_t)(r >> 4) * (K >> 4) + (c >> 4);
    const int lane = ((r & 7) << 2) + ((c >> 1) & 3);
    const int reg  = ((r >> 3) & 1) + (((c >> 3) & 1) << 1);
    return tile * 256 + (size_t)((lane << 2) + reg) * 2 + (c & 1);
}
// packed fp16 B-fragment offset (m16n8k16) for element (n, k) of N x K
__device__ __forceinline__ size_t boff16(int n, int k, int K) {
    const size_t tile = (size_t)(n >> 3) * (K >> 4) + (k >> 4);
    const int lane = ((n & 7) << 2) + ((k >> 1) & 3);
    const int reg  = (k >> 3) & 1;
    return tile * 128 + (size_t)((lane << 1) + reg) * 2 + (k & 1);
}
__device__ __forceinline__ __half2 split_pair(float v0, float v1, __half2& lo) {
    const __half h0 = __float2half_rn(v0);
    const __half h1 = __float2half_rn(v1);
    lo = __halves2half2(__float2half_rn(v0 - __half2float(h0)),
                        __float2half_rn(v1 - __half2float(h1)));
    return __halves2half2(h0, h1);
}

// ---------------- segment mean ----------------
__global__ void __launch_bounds__(256) seg_mean_kernel(const float* __restrict__ var_flat,
                                                       const int* __restrict__ seg) {
    __shared__ int s_bounds[2];
    __shared__ float red[8][32];
    const int b = blockIdx.x;
    const int tid = threadIdx.x;
    if (tid < 2) {
        const int v = b + tid;
        int lo = 0, hi = NT;
        while (lo < hi) {
            int mid = (lo + hi) >> 1;
            if (seg[mid] < v) lo = mid + 1; else hi = mid;
        }
        s_bounds[tid] = lo;
    }
    __syncthreads();
    const int start = s_bounds[0];
    const int end   = s_bounds[1];
    const int f = tid & 31;
    const int w = tid >> 5;
    float acc = 0.0f;
    for (int r = start + w; r < end; r += 8)
        acc += var_flat[(size_t)r * NF + f];
    red[w][f] = acc;
    __syncthreads();
    if (w == 0) {
        float s = 0.0f;
#pragma unroll
        for (int i = 0; i < 8; i++) s += red[i][f];
        const float cnt = fmaxf((float)(end - start), 1.0f);
        g_means[b * NF + f] = s / cnt;
    }
}

// ---------------- comb GEMM (K=32, fully resident): combined -> packed fp16 hi/lo ----------------
__global__ void __launch_bounds__(256, 2) sgemm_comb(const float* __restrict__ A,
                                                     const float* __restrict__ W,
                                                     const float* __restrict__ bias,
                                                     const float* __restrict__ addend,
                                                     __half* __restrict__ Phi,
                                                     __half* __restrict__ Plo) {
    __shared__ float As[NF][128];
    __shared__ float Bs[NF][128];
    const int bm  = blockIdx.y * 128;
    const int bn  = blockIdx.x * 128;
    const int tid = threadIdx.x;
    const int tx  = tid & 15;
    const int ty  = tid >> 4;

    // load tiles: 128 rows x 8 float4 each
#pragma unroll
    for (int it = 0; it < 4; it++) {
        const int idx = tid + it * 256;
        const int r = idx >> 3;
        const int q = idx & 7;
        const float4 av = *(const float4*)(A + (size_t)(bm + r) * NF + q * 4);
        const float4 wv = *(const float4*)(W + (size_t)(bn + r) * NF + q * 4);
        As[q * 4 + 0][r] = av.x; As[q * 4 + 1][r] = av.y;
        As[q * 4 + 2][r] = av.z; As[q * 4 + 3][r] = av.w;
        Bs[q * 4 + 0][r] = wv.x; Bs[q * 4 + 1][r] = wv.y;
        Bs[q * 4 + 2][r] = wv.z; Bs[q * 4 + 3][r] = wv.w;
    }

    // init acc with bias + addend (overlaps with smem fill latency)
    float acc[8][8];
    const float4 bv0 = *(const float4*)(bias + bn + tx * 8);
    const float4 bv1 = *(const float4*)(bias + bn + tx * 8 + 4);
#pragma unroll
    for (int i = 0; i < 8; i++) {
        const int m = bm + ty * 8 + i;
        const float4 a0 = *(const float4*)(addend + (size_t)m * ND + bn + tx * 8);
        const float4 a1 = *(const float4*)(addend + (size_t)m * ND + bn + tx * 8 + 4);
        acc[i][0] = a0.x + bv0.x; acc[i][1] = a0.y + bv0.y;
        acc[i][2] = a0.z + bv0.z; acc[i][3] = a0.w + bv0.w;
        acc[i][4] = a1.x + bv1.x; acc[i][5] = a1.y + bv1.y;
        acc[i][6] = a1.z + bv1.z; acc[i][7] = a1.w + bv1.w;
    }
    __syncthreads();

#pragma unroll
    for (int k = 0; k < NF; k++) {
        float a[8], bb[8];
#pragma unroll
        for (int i = 0; i < 8; i++) a[i] = As[k][ty * 8 + i];
#pragma unroll
        for (int j = 0; j < 8; j++) bb[j] = Bs[k][tx * 8 + j];
#pragma unroll
        for (int i = 0; i < 8; i++)
#pragma unroll
            for (int j = 0; j < 8; j++) acc[i][j] += a[i] * bb[j];
    }

#pragma unroll
    for (int i = 0; i < 8; i++) {
        const int m = bm + ty * 8 + i;
#pragma unroll
        for (int j = 0; j < 8; j += 2) {
            const int n = bn + tx * 8 + j;
            __half2 lo;
            const __half2 hi = split_pair(acc[i][j], acc[i][j + 1], lo);
            const size_t o = aoff16(m, n, ND) >> 1;
            ((__half2*)Phi)[o] = hi;
            ((__half2*)Plo)[o] = lo;
        }
    }
}

// ---------------- weight split into packed fp16 B-fragment layout (rows padded) ----------------
__global__ void __launch_bounds__(256) split_b_kernel(const float* __restrict__ W,
                                                      __half* __restrict__ hi,
                                                      __half* __restrict__ lo,
                                                      int rows, int K, int prows) {
    const size_t idx = (size_t)blockIdx.x * 256 + threadIdx.x;
    const size_t tot = (size_t)prows * (K >> 1);
    if (idx >= tot) return;
    const int n = (int)(idx / (K >> 1));
    const int k = (int)(idx % (K >> 1)) * 2;
    float v0 = 0.0f, v1 = 0.0f;
    if (n < rows) {
        v0 = W[(size_t)n * K + k];
        v1 = W[(size_t)n * K + k + 1];
    }
    __half2 l;
    const __half2 h = split_pair(v0, v1, l);
    const size_t o = boff16(n, k, K) >> 1;
    ((__half2*)hi)[o] = h;
    ((__half2*)lo)[o] = l;
}

// ---------------- fp16 2-split tensor-core GEMM (NT), CTA 128x256, BK=32, 3-stage ----------------
#define STAGE_BYTES 49152

#define LOADC(stg, ck) do {                                                          \
        const uint32_t _d0 = sbase + (uint32_t)(stg) * (uint32_t)STAGE_BYTES;        \
        _Pragma("unroll")                                                            \
        for (int _i = 0; _i < 12; _i++) {                                            \
            const int _u = tid + _i * 256;                                           \
            const __half* _src; uint32_t _dst;                                       \
            if (_u < 1024) {                                                         \
                const int _t = _u >> 9, _w = _u & 511;                               \
                const int _mt = _w >> 6, _rem = _w & 63;                             \
                _src = (_t ? Alo : Ahi)                                              \
                     + ((size_t)(mtile0 + _mt) * KB16 + 2 * (ck)) * 256 + _rem * 8;  \
                _dst = _d0 + _t * 8192 + _mt * 1024 + _rem * 16;                     \
            } else {                                                                 \
                const int _v = _u - 1024;                                            \
                const int _t = _v >> 10, _w = _v & 1023;                             \
                const int _nt = _w >> 5, _rem = _w & 31;                             \
                _src = (_t ? Blo : Bhi)                                              \
                     + ((size_t)(ntile0 + _nt) * KB16 + 2 * (ck)) * 128 + _rem * 8;  \
                _dst = _d0 + 16384 + _t * 16384 + _nt * 512 + _rem * 16;             \
            }                                                                        \
            cp16(_dst, _src);                                                        \
        }                                                                            \
        cp_commit();                                                                 \
    } while (0)

template <int KDIM, bool IS_G1>
__global__ void __launch_bounds__(256, 1) mma_gemm(
    const __half* __restrict__ Ahi, const __half* __restrict__ Alo,
    const __half* __restrict__ Bhi, const __half* __restrict__ Blo,
    const float* __restrict__ bias,
    float* __restrict__ Crow, __half* __restrict__ Phi, __half* __restrict__ Plo) {
    constexpr int KB16 = KDIM / 16;
    constexpr int NCH  = KDIM / 32;
    extern __shared__ __align__(16) char smem[];
    const int tid  = threadIdx.x;
    const int lane = tid & 31;
    const int wrp  = tid >> 5;
    const int warp_m = (wrp & 1) * 64;
    const int warp_n = (wrp >> 1) * 64;
    const int mtW = (wrp & 1) * 4;
    const int ntW = (wrp >> 1) * 8;
    const int bm = blockIdx.y * 128;
    const int bn = blockIdx.x * 256;
    const int mtile0 = blockIdx.y * 8;
    const int ntile0 = blockIdx.x * 32;
    const uint32_t sbase = smem_u32(smem);

    float acc[4][8][4];
#pragma unroll
    for (int a = 0; a < 4; a++)
#pragma unroll
        for (int b = 0; b < 8; b++)
#pragma unroll
            for (int c = 0; c < 4; c++) acc[a][b][c] = 0.0f;

    LOADC(0, 0);
    LOADC(1, 1);

#pragma unroll 1
    for (int ch = 0; ch < NCH; ch++) {
        if (ch + 2 < NCH) {
            LOADC((ch + 2) % 3, ch + 2);
            asm volatile("cp.async.wait_group 2;" ::: "memory");
        } else if (ch + 1 < NCH) {
            asm volatile("cp.async.wait_group 1;" ::: "memory");
        } else {
            asm volatile("cp.async.wait_group 0;" ::: "memory");
        }
        __syncthreads();
        const uint32_t stg = sbase + (uint32_t)(ch % 3) * (uint32_t)STAGE_BYTES;
#pragma unroll
        for (int kt = 0; kt < 2; kt++) {
            uint32_t ah[4][4], al[4][4];
#pragma unroll
            for (int mt = 0; mt < 4; mt++) {
                const uint32_t adr = stg + (mtW + mt) * 1024 + kt * 512 + lane * 16;
                lds128(ah[mt], adr);
                lds128(al[mt], adr + 8192);
            }
            // B double-buffer: prefetch nt+1 while issuing MMAs for nt;
            // product-major, mt-inner => dependent acc pairs separated by 3 indep MMAs
            uint32_t bh[2][2], bl[2][2];
            {
                const uint32_t b0 = stg + 16384 + ntW * 512 + kt * 256 + lane * 8;
                lds64(bh[0], b0);
                lds64(bl[0], b0 + 16384);
            }
#pragma unroll
            for (int nt = 0; nt < 8; nt++) {
                const int cur = nt & 1;
                if (nt < 7) {
                    const uint32_t bnx = stg + 16384 + (ntW + nt + 1) * 512 + kt * 256 + lane * 8;
                    lds64(bh[cur ^ 1], bnx);
                    lds64(bl[cur ^ 1], bnx + 16384);
                }
#pragma unroll
                for (int mt = 0; mt < 4; mt++) mma16(acc[mt][nt], ah[mt], bh[cur]);
#pragma unroll
                for (int mt = 0; mt < 4; mt++) mma16(acc[mt][nt], ah[mt], bl[cur]);
#pragma unroll
                for (int mt = 0; mt < 4; mt++) mma16(acc[mt][nt], al[mt], bh[cur]);
            }
        }
        __syncthreads();
    }

    // epilogue
    const int g  = lane >> 2;
    const int tg = lane & 3;
#pragma unroll
    for (int mt = 0; mt < 4; mt++) {
#pragma unroll
        for (int nt = 0; nt < 8; nt++) {
            const int col0 = bn + warp_n + nt * 8 + tg * 2;
            const int row0 = bm + warp_m + mt * 16 + g;
#pragma unroll
            for (int half = 0; half < 2; half++) {
                const int row = row0 + half * 8;
                float v0 = acc[mt][nt][half * 2 + 0];
                float v1 = acc[mt][nt][half * 2 + 1];
                if (IS_G1) {
                    v0 = fmaxf(v0 + __ldg(&bias[col0]), 0.0f);
                    v1 = fmaxf(v1 + __ldg(&bias[col0 + 1]), 0.0f);
                    Crow[(size_t)row * NH + col0]     = v0;
                    Crow[(size_t)row * NH + col0 + 1] = v1;
                    __half2 lo;
                    const __half2 hi = split_pair(v0, v1, lo);
                    const size_t o = aoff16(row, col0, NH) >> 1;
                    ((__half2*)Phi)[o] = hi;
                    ((__half2*)Plo)[o] = lo;
                } else {
                    if (col0 < NC)
                        Crow[(size_t)row * NC + col0] = v0 + __ldg(&bias[col0]);
                    if (col0 + 1 < NC)
                        Crow[(size_t)row * NC + col0 + 1] = v1 + __ldg(&bias[col0 + 1]);
                }
            }
        }
    }
}

// ---------------- scalar head ----------------
__global__ void __launch_bounds__(256) scalar_kernel(const float* __restrict__ Ws,
                                                     const float* __restrict__ bs) {
    const int warp = threadIdx.x >> 5;
    const int lane = threadIdx.x & 31;
    const int b = blockIdx.x * 8 + warp;
    const float* hrow = g_hidden + (size_t)b * NH;
    float acc = 0.0f;
    for (int k = lane; k < NH; k += 32) acc += hrow[k] * __ldg(&Ws[k]);
#pragma unroll
    for (int o = 16; o > 0; o >>= 1) acc += __shfl_down_sync(0xffffffffu, acc, o);
    if (lane == 0) g_scalar[b] = acc + bs[0];
}

// ---------------- per-row logsumexp + argmax ----------------
__global__ void __launch_bounds__(256) loss_row_kernel(const int* __restrict__ target) {
    __shared__ float sval[256];
    __shared__ int   sidx[256];
    __shared__ float ssum[256];
    const int b = blockIdx.x;
    const int tid = threadIdx.x;
    const float* row = g_logits + (size_t)b * NC;

    float mval = -3.402823466e38f;
    int midx = 0;
    for (int c = tid; c < NC; c += 256) {
        const float v = row[c];
        if (v > mval) { mval = v; midx = c; }
    }
    sval[tid] = mval; sidx[tid] = midx;
    __syncthreads();
    for (int s = 128; s > 0; s >>= 1) {
        if (tid < s) {
            const float v2 = sval[tid + s];
            const int   i2 = sidx[tid + s];
            if (v2 > sval[tid] || (v2 == sval[tid] && i2 < sidx[tid])) {
                sval[tid] = v2; sidx[tid] = i2;
            }
        }
        __syncthreads();
    }
    const float maxv = sval[0];
    const int   amax = sidx[0];

    // exp terms with d < -20 contribute < 1000*e^-20 ~ 2e-6 absolute vs sum >= 1: skip
    float lsum = 0.0f;
    for (int c = tid; c < NC; c += 256) {
        const float d = row[c] - maxv;
        if (d > -20.0f) lsum += __expf(d);
    }
    ssum[tid] = lsum;
    __syncthreads();
    for (int s = 128; s > 0; s >>= 1) {
        if (tid < s) ssum[tid] += ssum[tid + s];
        __syncthreads();
    }
    if (tid == 0) {
        const int t = target[b];
        g_row_lv[b]  = maxv + logf(ssum[0]) - row[t];
        g_row_acc[b] = (amax == t) ? 1.0f : 0.0f;
    }
}

// ---------------- final reduce ----------------
__global__ void __launch_bounds__(1024) final_kernel(const float* __restrict__ target_scalar,
                                                     float* __restrict__ out) {
    __shared__ float s_lv[1024];
    __shared__ float s_ac[1024];
    __shared__ float s_sq[1024];
    const int tid = threadIdx.x;
    float lv = 0.0f, ac = 0.0f, sq = 0.0f;
    for (int b = tid; b < NB; b += 1024) {
        lv += g_row_lv[b];
        ac += g_row_acc[b];
        const float d = g_scalar[b] - target_scalar[b];
        sq += d * d;
    }
    s_lv[tid] = lv; s_ac[tid] = ac; s_sq[tid] = sq;
    __syncthreads();
    for (int s = 512; s > 0; s >>= 1) {
        if (tid < s) {
            s_lv[tid] += s_lv[tid + s];
            s_ac[tid] += s_ac[tid + s];
            s_sq[tid] += s_sq[tid + s];
        }
        __syncthreads();
    }
    if (tid == 0) {
        const float lvm  = s_lv[0] / (float)NB;
        const float sqm  = s_sq[0] / (float)NB;
        const float accm = s_ac[0] / (float)NB;
        out[0] = lvm + sqm;
        out[1] = lvm;
        out[2] = sqm;
        out[3] = accm;
    }
}

// ---------------- launch ----------------
extern "C" void kernel_launch(void* const* d_in, const int* in_sizes, int n_in,
                              void* d_out, int out_size) {
    const float* feature  = (const float*)d_in[0];
    const float* var_flat = (const float*)d_in[1];
    const int*   seg      = (const int*)d_in[2];
    const int*   target_v = (const int*)d_in[3];
    const float* target_s = (const float*)d_in[4];
    const float* Wv       = (const float*)d_in[5];
    const float* bv       = (const float*)d_in[6];
    const float* W1       = (const float*)d_in[7];
    const float* b1       = (const float*)d_in[8];
    const float* W2       = (const float*)d_in[9];
    const float* b2       = (const float*)d_in[10];
    const float* Ws       = (const float*)d_in[11];
    const float* bs       = (const float*)d_in[12];
    float* out = (float*)d_out;

    float *p_means, *p_hid, *p_log;
    __half *p_a1h, *p_a1l, *p_w1h, *p_w1l, *p_a2h, *p_a2l, *p_w2h, *p_w2l;
    cudaGetSymbolAddress((void**)&p_means, g_means);
    cudaGetSymbolAddress((void**)&p_a1h,   g_a1_hi);
    cudaGetSymbolAddress((void**)&p_a1l,   g_a1_lo);
    cudaGetSymbolAddress((void**)&p_w1h,   g_w1_hi);
    cudaGetSymbolAddress((void**)&p_w1l,   g_w1_lo);
    cudaGetSymbolAddress((void**)&p_a2h,   g_a2_hi);
    cudaGetSymbolAddress((void**)&p_a2l,   g_a2_lo);
    cudaGetSymbolAddress((void**)&p_w2h,   g_w2_hi);
    cudaGetSymbolAddress((void**)&p_w2l,   g_w2_lo);
    cudaGetSymbolAddress((void**)&p_hid,   g_hidden);
    cudaGetSymbolAddress((void**)&p_log,   g_logits);

    const int SMEM_GEMM = 3 * STAGE_BYTES;  // 147456
    cudaFuncSetAttribute(mma_gemm<1024, true>,
                         cudaFuncAttributeMaxDynamicSharedMemorySize, SMEM_GEMM);
    cudaFuncSetAttribute(mma_gemm<2048, false>,
                         cudaFuncAttributeMaxDynamicSharedMemorySize, SMEM_GEMM);

    // 1) ragged per-segment mean
    seg_mean_kernel<<<NB, 256>>>(var_flat, seg);

    // 2) weight splits into packed fp16 B-fragment layout
    {
        size_t n1 = (size_t)NH * ND / 2;
        split_b_kernel<<<(int)((n1 + 255) / 256), 256>>>(W1, p_w1h, p_w1l, NH, ND, NH);
        size_t n2 = (size_t)NCPAD * NH / 2;
        split_b_kernel<<<(int)((n2 + 255) / 256), 256>>>(W2, p_w2h, p_w2l, NC, NH, NCPAD);
    }

    // 3) combined = means@Wv^T + bv + feature -> packed fp16 A hi/lo
    sgemm_comb<<<dim3(ND / 128, NB / 128), 256>>>(
        p_means, Wv, bv, feature, p_a1h, p_a1l);

    // 4) hidden = relu(combined@W1^T + b1)  [mma.sync fp16 2-split]
    mma_gemm<1024, true><<<dim3(NH / 256, NB / 128), 256, SMEM_GEMM>>>(
        p_a1h, p_a1l, p_w1h, p_w1l, b1, p_hid, p_a2h, p_a2l);

    // 5) logits = hidden@W2^T + b2  [mma.sync fp16 2-split], N guard 1000
    mma_gemm<2048, false><<<dim3(NCPAD / 256, NB / 128), 256, SMEM_GEMM>>>(
        p_a2h, p_a2l, p_w2h, p_w2l, b2, p_log, nullptr, nullptr);

    // 6) scalar head
    scalar_kernel<<<NB / 8, 256>>>(Ws, bs);

    // 7) per-row softmax stats
    loss_row_kernel<<<NB, 256>>>(target_v);

    // 8) final reduce
    final_kernel<<<1, 1024>>>(target_s, out);
}